// round 10
// baseline (speedup 1.0000x reference)
#include <cuda_runtime.h>
#include <cuda_bf16.h>
#include <math.h>
#include <stdint.h>

#define BATCH 2048
#define DM    256
#define NF    32768
#define KB    8
#define CHUNK 1024
#define MAX_ITEMS 48
#define KPH   36          // row stride in uint32 (half2) units; 144B, 16B-aligned

// ---------------- device globals ----------------
__device__ __nv_bfloat16 g_xn[BATCH * DM];              // bf16 xn (GEMM A)
__device__ float         g_xn32[BATCH * DM];            // fp32 xn (MSE target)
__device__ __nv_bfloat16 g_acts[(size_t)BATCH * NF];    // bf16 acts
__device__ __nv_bfloat16 g_WencT[(size_t)NF * DM];      // [f][d] bf16
__device__ __nv_bfloat16 g_WdecT[(size_t)DM * NF];      // [d][f] bf16
__device__ __nv_bfloat16 g_part[(size_t)MAX_ITEMS * BATCH * DM];   // bf16 partials
__device__ float g_wdn10[NF];
__device__ float g_cwseg[NF];
__device__ float g_cw[KB];
__device__ float g_normpart[BATCH / 8];
__device__ float g_scale, g_l1sum, g_l0sum;
__device__ float g_errsum[KB];
__device__ int   g_items[4 * MAX_ITEMS];                // fs, len, blk, last-in-block

// ---------------- helpers ----------------
__device__ __forceinline__ void cp16(uint32_t dst, const void* src) {
    asm volatile("cp.async.cg.shared.global [%0], [%1], 16;" :: "r"(dst), "l"(src));
}
#define CP_COMMIT() asm volatile("cp.async.commit_group;" ::: "memory")
#define CP_WAIT1()  asm volatile("cp.async.wait_group 1;" ::: "memory")
#define CP_WAIT0()  asm volatile("cp.async.wait_group 0;" ::: "memory")

__device__ __forceinline__ void mma16(float* c, const uint32_t* a, const uint32_t* b) {
    asm volatile(
        "mma.sync.aligned.m16n8k16.row.col.f32.bf16.bf16.f32 "
        "{%0,%1,%2,%3}, {%4,%5,%6,%7}, {%8,%9}, {%0,%1,%2,%3};"
        : "+f"(c[0]), "+f"(c[1]), "+f"(c[2]), "+f"(c[3])
        : "r"(a[0]), "r"(a[1]), "r"(a[2]), "r"(a[3]), "r"(b[0]), "r"(b[1]));
}

// warp-tile 32(m) x 64(n), k-chunk 64 bf16 (32 half2), tiles A[128][KPH], B[128][KPH]
__device__ __forceinline__ void compute_chunk(const uint32_t* ap, const uint32_t* bp,
                                              int rm, int rn, int grp, int qid,
                                              float c[2][8][4]) {
    #pragma unroll
    for (int kk = 0; kk < 32; kk += 8) {        // 4 x k16 steps (8 half2 each)
        uint32_t a[2][4];
        #pragma unroll
        for (int mi = 0; mi < 2; mi++) {
            int r0 = rm + mi * 16 + grp;
            a[mi][0] = ap[r0 * KPH + kk + qid];
            a[mi][1] = ap[(r0 + 8) * KPH + kk + qid];
            a[mi][2] = ap[r0 * KPH + kk + qid + 4];
            a[mi][3] = ap[(r0 + 8) * KPH + kk + qid + 4];
        }
        #pragma unroll
        for (int ni = 0; ni < 8; ni++) {
            int col = rn + ni * 8 + grp;
            uint32_t b[2] = { bp[col * KPH + kk + qid], bp[col * KPH + kk + qid + 4] };
            mma16(c[0][ni], a[0], b);
            mma16(c[1][ni], a[1], b);
        }
    }
}

// ---------------- small kernels ----------------
// per-block partial of sum of row norms (no pre-zero needed)
__global__ void k_norms(const float* __restrict__ x) {
    __shared__ float wsum[8];
    int warp = threadIdx.x >> 5, lane = threadIdx.x & 31;
    int row = blockIdx.x * 8 + warp;
    const float* p = x + row * DM + lane * 8;
    float4 v0 = *(const float4*)p;
    float4 v1 = *(const float4*)(p + 4);
    float s = v0.x*v0.x + v0.y*v0.y + v0.z*v0.z + v0.w*v0.w
            + v1.x*v1.x + v1.y*v1.y + v1.z*v1.z + v1.w*v1.w;
    #pragma unroll
    for (int o = 16; o > 0; o >>= 1) s += __shfl_down_sync(0xffffffffu, s, o);
    if (lane == 0) wsum[warp] = sqrtf(s);
    __syncthreads();
    if (threadIdx.x == 0) {
        float t = 0.f;
        #pragma unroll
        for (int i = 0; i < 8; i++) t += wsum[i];
        g_normpart[blockIdx.x] = t;
    }
}

__global__ void k_prep(const float* __restrict__ ravg, const float* __restrict__ w) {
    __shared__ float red[256];
    int tid = threadIdx.x;
    red[tid] = g_normpart[tid];
    __syncthreads();
    for (int s = 128; s > 0; s >>= 1) {
        if (tid < s) red[tid] += red[tid + s];
        __syncthreads();
    }
    if (tid == 0) {
        float mean = red[0] / (float)BATCH;
        float ra = 0.99f * ravg[0] + 0.01f * mean;
        g_scale = 16.0f / ra;
        float s = 0.0f;
        for (int j = KB - 1; j >= 0; j--) { s += w[j]; g_cw[j] = s / (float)KB; }
        g_l1sum = 0.f; g_l0sum = 0.f;
    }
}

// fused: W_dec row norms + cw[seg] (blocks 0..NF/8-1), xn scaling (rest)
__global__ void k_wdnxn(const float* __restrict__ Wdec, const int* __restrict__ seg,
                        const float* __restrict__ x) {
    if (blockIdx.x < NF / 8) {
        int warp = threadIdx.x >> 5, lane = threadIdx.x & 31;
        int f = blockIdx.x * 8 + warp;
        const float* p = Wdec + f * DM + lane * 8;
        float4 v0 = *(const float4*)p;
        float4 v1 = *(const float4*)(p + 4);
        float s = v0.x*v0.x + v0.y*v0.y + v0.z*v0.z + v0.w*v0.w
                + v1.x*v1.x + v1.y*v1.y + v1.z*v1.z + v1.w*v1.w;
        #pragma unroll
        for (int o = 16; o > 0; o >>= 1) s += __shfl_down_sync(0xffffffffu, s, o);
        if (lane == 0) {
            g_wdn10[f] = 10.0f * sqrtf(s);
            g_cwseg[f] = g_cw[seg[f]];
        }
    } else {
        int i = (blockIdx.x - NF / 8) * 256 + threadIdx.x;
        float v = x[i] * g_scale;
        g_xn32[i] = v;
        g_xn[i] = __float2bfloat16(v);
    }
}

__global__ void k_worklist(const int* __restrict__ seg) {
    __shared__ int bpos[16];
    __shared__ int bcnt;
    int tid = threadIdx.x;
    if (tid == 0) bcnt = 0;
    if (tid < KB) g_errsum[tid] = 0.f;
    __syncthreads();
    for (int f = tid + 1; f < NF; f += blockDim.x) {
        if (seg[f] != seg[f - 1]) {
            int i = atomicAdd(&bcnt, 1);
            if (i < 16) bpos[i] = f;
        }
    }
    __syncthreads();
    if (tid == 0) {
        int n = bcnt < 16 ? bcnt : 16;
        for (int i = 1; i < n; i++) {
            int v = bpos[i], j = i - 1;
            while (j >= 0 && bpos[j] > v) { bpos[j + 1] = bpos[j]; j--; }
            bpos[j + 1] = v;
        }
        int cur = 0, bi = 0, ni = 0;
        while (cur < NF && ni < MAX_ITEMS) {
            int nxt = ((cur / CHUNK) + 1) * CHUNK;
            while (bi < n && bpos[bi] <= cur) bi++;
            if (bi < n && bpos[bi] < nxt) nxt = bpos[bi];
            g_items[ni * 4 + 0] = cur;
            g_items[ni * 4 + 1] = nxt - cur;
            g_items[ni * 4 + 2] = seg[cur];
            g_items[ni * 4 + 3] = 0;
            ni++; cur = nxt;
        }
        for (int i = 0; i < ni; i++)
            g_items[i * 4 + 3] = (i == ni - 1) || (g_items[(i + 1) * 4 + 2] != g_items[i * 4 + 2]);
        for (; ni < MAX_ITEMS; ni++) g_items[ni * 4 + 1] = 0;
    }
}

// transpose src[R][C] -> dst[C][R], fp32 -> bf16
__global__ void k_transpose(const float* __restrict__ src, int R, int C, int which) {
    __shared__ float t[32][33];
    __nv_bfloat16* dst = which ? g_WdecT : g_WencT;
    int bx = blockIdx.x * 32, by = blockIdx.y * 32;
    int x = threadIdx.x, y = threadIdx.y;
    #pragma unroll
    for (int j = 0; j < 32; j += 8) t[y + j][x] = src[(size_t)(by + y + j) * C + bx + x];
    __syncthreads();
    #pragma unroll
    for (int j = 0; j < 32; j += 8)
        dst[(size_t)(bx + y + j) * R + by + x] = __float2bfloat16(t[x][y + j]);
}

// ---------------- encode ----------------
// SMEM bytes: A0@0, A1@18432, B0@36864, B1@55296, sArr@73728 (1536B)
#define ENC_SMEM (73728 + 1536)
#define DEC_SMEM 73728

__device__ __forceinline__ void enc_issue(uint32_t Ab, uint32_t Bb, int tid,
                                          int m0, int n0, int k0) {
    #pragma unroll
    for (int i = 0; i < 4; i++) {
        int slot = tid + i * 256, row = slot >> 3, c4 = slot & 7;
        uint32_t off = (uint32_t)(row * 144 + c4 * 16);
        cp16(Ab + off, &g_xn[(m0 + row) * DM + k0 + c4 * 8]);
        cp16(Bb + off, &g_WencT[(size_t)(n0 + row) * DM + k0 + c4 * 8]);
    }
    CP_COMMIT();
}

__global__ void __launch_bounds__(256, 2) k_encode(const float* __restrict__ benc) {
    extern __shared__ char smc[];
    uint32_t sb = (uint32_t)__cvta_generic_to_shared(smc);
    const uint32_t* Abuf[2] = { (uint32_t*)smc, (uint32_t*)(smc + 18432) };
    const uint32_t* Bbuf[2] = { (uint32_t*)(smc + 36864), (uint32_t*)(smc + 55296) };
    uint32_t Ab[2] = { sb, sb + 18432 };
    uint32_t Bb[2] = { sb + 36864, sb + 55296 };
    float* sArr = (float*)(smc + 73728);

    int tid = threadIdx.x, wid = tid >> 5, lane = tid & 31;
    int grp = lane >> 2, qid = lane & 3;
    int m0 = blockIdx.x * 128, n0 = blockIdx.y * 128;
    int rm = (wid & 3) * 32, rn = (wid >> 2) * 64;

    if (tid < 128) {
        sArr[tid]       = benc[n0 + tid];
        sArr[128 + tid] = g_wdn10[n0 + tid];
        sArr[256 + tid] = g_cwseg[n0 + tid];
    }

    float c[2][8][4];
    #pragma unroll
    for (int i = 0; i < 2; i++)
        #pragma unroll
        for (int j = 0; j < 8; j++)
            #pragma unroll
            for (int q = 0; q < 4; q++) c[i][j][q] = 0.f;

    enc_issue(Ab[0], Bb[0], tid, m0, n0, 0);

    #pragma unroll 1
    for (int s = 0; s < 4; s++) {               // K=256, 4 chunks of 64
        if (s < 3) { enc_issue(Ab[(s + 1) & 1], Bb[(s + 1) & 1], tid, m0, n0, (s + 1) * 64); CP_WAIT1(); }
        else       { CP_WAIT0(); }
        __syncthreads();
        compute_chunk(Abuf[s & 1], Bbuf[s & 1], rm, rn, grp, qid, c);
        __syncthreads();
    }

    // epilogue: bias + relu + fused l1/l0, store bf16 acts
    float l1loc = 0.f;
    int l0loc = 0;
    #pragma unroll
    for (int mi = 0; mi < 2; mi++) {
        #pragma unroll
        for (int ni = 0; ni < 8; ni++) {
            int mg = m0 + rm + mi * 16 + grp;
            int nl = rn + ni * 8 + qid * 2;
            float be0 = sArr[nl], be1 = sArr[nl + 1];
            float wd0 = sArr[128 + nl], wd1 = sArr[128 + nl + 1];
            float cw0 = sArr[256 + nl], cw1 = sArr[256 + nl + 1];
            #pragma unroll
            for (int h = 0; h < 2; h++) {
                int m = mg + h * 8;
                float a0 = fmaxf(c[mi][ni][h * 2 + 0] + be0, 0.f);
                float a1 = fmaxf(c[mi][ni][h * 2 + 1] + be1, 0.f);
                l1loc += __logf(fmaf(a0, wd0, 1.f)) * cw0
                       + __logf(fmaf(a1, wd1, 1.f)) * cw1;
                l0loc += (a0 > 0.f) + (a1 > 0.f);
                *(__nv_bfloat162*)&g_acts[(size_t)m * NF + n0 + nl] =
                    __floats2bfloat162_rn(a0, a1);
            }
        }
    }
    float l0f = (float)l0loc;
    #pragma unroll
    for (int o = 16; o > 0; o >>= 1) {
        l1loc += __shfl_down_sync(0xffffffffu, l1loc, o);
        l0f   += __shfl_down_sync(0xffffffffu, l0f, o);
    }
    if (lane == 0) { atomicAdd(&g_l1sum, l1loc); atomicAdd(&g_l0sum, l0f); }
}

// ---------------- decode ----------------
// bf16: fa = fs & ~7 (16B alignment); valid features [fs, fe); edges via scalar path.
__device__ __forceinline__ void dec_issue(uint32_t Ab, uint32_t Bb,
                                          __nv_bfloat16* Af, __nv_bfloat16* Bf,
                                          int tid, int m0, int d0,
                                          int fa, int lo, int hi, int k0) {
    int lo8 = lo ? 8 : 0;
    #pragma unroll
    for (int i = 0; i < 4; i++) {
        int slot = tid + i * 256, row = slot >> 3, c4 = slot & 7;
        int kb = k0 + c4 * 8;
        uint32_t off = (uint32_t)(row * 144 + c4 * 16);
        if (kb >= lo8 && kb + 7 < hi) {
            cp16(Ab + off, &g_acts[(size_t)(m0 + row) * NF + fa + kb]);
            cp16(Bb + off, &g_WdecT[(size_t)(d0 + row) * NF + fa + kb]);
        } else {
            #pragma unroll
            for (int e = 0; e < 8; e++) {
                int k = kb + e;
                bool v = (k >= lo) && (k < hi);
                __nv_bfloat16 av = v ? g_acts[(size_t)(m0 + row) * NF + fa + k] : __nv_bfloat16(0.f);
                __nv_bfloat16 bv = v ? g_WdecT[(size_t)(d0 + row) * NF + fa + k] : __nv_bfloat16(0.f);
                Af[row * 72 + c4 * 8 + e] = av;
                Bf[row * 72 + c4 * 8 + e] = bv;
            }
        }
    }
    CP_COMMIT();
}

__global__ void __launch_bounds__(256, 2) k_decode() {
    int item = blockIdx.z;
    int fs = g_items[item * 4 + 0], len = g_items[item * 4 + 1];
    if (len == 0) return;
    int fa = fs & ~7;
    int fe = fs + len;
    int lo = fs - fa, hi = fe - fa;
    int ns = (hi + 63) >> 6;

    extern __shared__ char smc[];
    uint32_t sb = (uint32_t)__cvta_generic_to_shared(smc);
    const uint32_t* Abuf[2] = { (uint32_t*)smc, (uint32_t*)(smc + 18432) };
    const uint32_t* Bbuf[2] = { (uint32_t*)(smc + 36864), (uint32_t*)(smc + 55296) };
    __nv_bfloat16* Afh[2] = { (__nv_bfloat16*)smc, (__nv_bfloat16*)(smc + 18432) };
    __nv_bfloat16* Bfh[2] = { (__nv_bfloat16*)(smc + 36864), (__nv_bfloat16*)(smc + 55296) };
    uint32_t Ab[2] = { sb, sb + 18432 };
    uint32_t Bb[2] = { sb + 36864, sb + 55296 };

    int tid = threadIdx.x, wid = tid >> 5, lane = tid & 31;
    int grp = lane >> 2, qid = lane & 3;
    int m0 = blockIdx.y * 128, d0 = blockIdx.x * 128;
    int rm = (wid & 3) * 32, rn = (wid >> 2) * 64;

    float c[2][8][4];
    #pragma unroll
    for (int i = 0; i < 2; i++)
        #pragma unroll
        for (int j = 0; j < 8; j++)
            #pragma unroll
            for (int q = 0; q < 4; q++) c[i][j][q] = 0.f;

    dec_issue(Ab[0], Bb[0], Afh[0], Bfh[0], tid, m0, d0, fa, lo, hi, 0);

    #pragma unroll 1
    for (int s = 0; s < ns; s++) {
        if (s + 1 < ns) {
            dec_issue(Ab[(s + 1) & 1], Bb[(s + 1) & 1], Afh[(s + 1) & 1], Bfh[(s + 1) & 1],
                      tid, m0, d0, fa, lo, hi, (s + 1) * 64);
            CP_WAIT1();
        } else {
            CP_WAIT0();
        }
        __syncthreads();
        compute_chunk(Abuf[s & 1], Bbuf[s & 1], rm, rn, grp, qid, c);
        __syncthreads();
    }

    __nv_bfloat16* pbase = &g_part[(size_t)item * BATCH * DM];
    #pragma unroll
    for (int mi = 0; mi < 2; mi++) {
        #pragma unroll
        for (int ni = 0; ni < 8; ni++) {
            int mg = m0 + rm + mi * 16 + grp;
            int col = d0 + rn + ni * 8 + qid * 2;
            *(__nv_bfloat162*)&pbase[(size_t)mg * DM + col] =
                __floats2bfloat162_rn(c[mi][ni][0], c[mi][ni][1]);
            *(__nv_bfloat162*)&pbase[(size_t)(mg + 8) * DM + col] =
                __floats2bfloat162_rn(c[mi][ni][2], c[mi][ni][3]);
        }
    }
}

// ---------------- cumulative item sum + per-block squared error ----------------
__global__ void k_err(const float* __restrict__ bdec) {
    int b = blockIdx.x, d = threadIdx.x;
    __shared__ float red[256];
    float xnv = g_xn32[b * DM + d];
    float cum = bdec[d];
    for (int i = 0; i < MAX_ITEMS; i++) {
        int len = g_items[i * 4 + 1];
        if (len == 0) break;
        cum += __bfloat162float(g_part[(size_t)i * BATCH * DM + (size_t)b * DM + d]);
        if (g_items[i * 4 + 3]) {
            float e = cum - xnv;
            red[d] = e * e;
            __syncthreads();
            for (int s = 128; s > 0; s >>= 1) {
                if (d < s) red[d] += red[d + s];
                __syncthreads();
            }
            if (d == 0) atomicAdd(&g_errsum[g_items[i * 4 + 2]], red[0]);
            __syncthreads();
        }
    }
}

__global__ void k_final(const float* __restrict__ w, const float* __restrict__ l1_scale,
                        float* __restrict__ out) {
    float mse = 0.0f;
    for (int k = 0; k < KB; k++) mse += (g_errsum[k] / (float)BATCH) * w[k];
    mse /= (float)KB;
    float l1 = g_l1sum / (float)BATCH;
    float avg_l0 = g_l0sum / (float)BATCH;
    float s = (avg_l0 < 100.0f) ? l1_scale[0] * (1.0f - 3e-4f)
                                : l1_scale[0] * (1.0f + 3e-4f);
    out[0] = mse + s * l1;
}

// ---------------- launch ----------------
extern "C" void kernel_launch(void* const* d_in, const int* in_sizes, int n_in,
                              void* d_out, int out_size) {
    const float* x    = (const float*)d_in[0];
    const float* Wenc = (const float*)d_in[1];
    const float* benc = (const float*)d_in[2];
    const float* Wdec = (const float*)d_in[3];
    const float* bdec = (const float*)d_in[4];
    const float* bw   = (const float*)d_in[5];
    const float* ravg = (const float*)d_in[6];
    const float* l1s  = (const float*)d_in[7];
    const int*   seg  = (const int*)d_in[8];
    float* out = (float*)d_out;

    cudaFuncSetAttribute(k_encode, cudaFuncAttributeMaxDynamicSharedMemorySize, ENC_SMEM);
    cudaFuncSetAttribute(k_decode, cudaFuncAttributeMaxDynamicSharedMemorySize, DEC_SMEM);

    k_transpose<<<dim3(NF / 32, DM / 32), dim3(32, 8)>>>(Wenc, DM, NF, 0);   // 0
    k_transpose<<<dim3(DM / 32, NF / 32), dim3(32, 8)>>>(Wdec, NF, DM, 1);   // 1
    k_norms<<<BATCH / 8, 256>>>(x);                                          // 2
    k_prep<<<1, 256>>>(ravg, bw);                                            // 3
    k_wdnxn<<<NF / 8 + BATCH * DM / 256, 256>>>(Wdec, seg, x);               // 4
    k_encode<<<dim3(16, 256), 256, ENC_SMEM>>>(benc);                        // 5  <- ncu capture
    k_worklist<<<1, 256>>>(seg);                                             // 6
    k_decode<<<dim3(2, 16, MAX_ITEMS), 256, DEC_SMEM>>>();                   // 7
    k_err<<<BATCH, 256>>>(bdec);                                             // 8
    k_final<<<1, 1>>>(bw, l1s, out);                                         // 9
}

// round 11
// speedup vs baseline: 1.1512x; 1.1512x over previous
#include <cuda_runtime.h>
#include <cuda_bf16.h>
#include <math.h>
#include <stdint.h>

#define BATCH 2048
#define DM    256
#define NF    32768
#define KB    8
#define CHUNK 1024
#define MAX_ITEMS 48
#define KPH   36          // row stride in uint32 (half2) units; 144B, 16B-aligned
#define STG   36864u      // bytes per pipeline stage (A 18432 + B 18432)

// ---------------- device globals ----------------
__device__ __nv_bfloat16 g_xn[BATCH * DM];              // bf16 xn (GEMM A)
__device__ float         g_xn32[BATCH * DM];            // fp32 xn (MSE target)
__device__ __nv_bfloat16 g_acts[(size_t)BATCH * NF];    // bf16 acts
__device__ __nv_bfloat16 g_WencT[(size_t)NF * DM];      // [f][d] bf16
__device__ __nv_bfloat16 g_WdecT[(size_t)DM * NF];      // [d][f] bf16
__device__ __nv_bfloat16 g_part[(size_t)MAX_ITEMS * BATCH * DM];   // bf16 partials
__device__ float g_wdn10[NF];
__device__ float g_cwseg[NF];
__device__ float g_cw[KB];
__device__ float g_normpart[BATCH / 8];
__device__ float g_scale, g_l1sum, g_l0sum;
__device__ float g_errsum[KB];
__device__ int   g_items[4 * MAX_ITEMS];                // fs, len, blk, last-in-block

// ---------------- helpers ----------------
__device__ __forceinline__ void cp16(uint32_t dst, const void* src) {
    asm volatile("cp.async.cg.shared.global [%0], [%1], 16;" :: "r"(dst), "l"(src));
}
#define CP_COMMIT() asm volatile("cp.async.commit_group;" ::: "memory")
#define CP_WAIT1()  asm volatile("cp.async.wait_group 1;" ::: "memory")

__device__ __forceinline__ void mma16(float* c, const uint32_t* a, const uint32_t* b) {
    asm volatile(
        "mma.sync.aligned.m16n8k16.row.col.f32.bf16.bf16.f32 "
        "{%0,%1,%2,%3}, {%4,%5,%6,%7}, {%8,%9}, {%0,%1,%2,%3};"
        : "+f"(c[0]), "+f"(c[1]), "+f"(c[2]), "+f"(c[3])
        : "r"(a[0]), "r"(a[1]), "r"(a[2]), "r"(a[3]), "r"(b[0]), "r"(b[1]));
}

// warp-tile 32(m) x 64(n), k-chunk 64 bf16 (32 half2), tiles A[128][KPH], B[128][KPH]
__device__ __forceinline__ void compute_chunk(const uint32_t* ap, const uint32_t* bp,
                                              int rm, int rn, int grp, int qid,
                                              float c[2][8][4]) {
    #pragma unroll
    for (int kk = 0; kk < 32; kk += 8) {        // 4 x k16 steps (8 half2 each)
        uint32_t a[2][4];
        #pragma unroll
        for (int mi = 0; mi < 2; mi++) {
            int r0 = rm + mi * 16 + grp;
            a[mi][0] = ap[r0 * KPH + kk + qid];
            a[mi][1] = ap[(r0 + 8) * KPH + kk + qid];
            a[mi][2] = ap[r0 * KPH + kk + qid + 4];
            a[mi][3] = ap[(r0 + 8) * KPH + kk + qid + 4];
        }
        #pragma unroll
        for (int ni = 0; ni < 8; ni++) {
            int col = rn + ni * 8 + grp;
            uint32_t b[2] = { bp[col * KPH + kk + qid], bp[col * KPH + kk + qid + 4] };
            mma16(c[0][ni], a[0], b);
            mma16(c[1][ni], a[1], b);
        }
    }
}

// ---------------- small kernels ----------------
__global__ void k_norms(const float* __restrict__ x) {
    __shared__ float wsum[8];
    int warp = threadIdx.x >> 5, lane = threadIdx.x & 31;
    int row = blockIdx.x * 8 + warp;
    const float* p = x + row * DM + lane * 8;
    float4 v0 = *(const float4*)p;
    float4 v1 = *(const float4*)(p + 4);
    float s = v0.x*v0.x + v0.y*v0.y + v0.z*v0.z + v0.w*v0.w
            + v1.x*v1.x + v1.y*v1.y + v1.z*v1.z + v1.w*v1.w;
    #pragma unroll
    for (int o = 16; o > 0; o >>= 1) s += __shfl_down_sync(0xffffffffu, s, o);
    if (lane == 0) wsum[warp] = sqrtf(s);
    __syncthreads();
    if (threadIdx.x == 0) {
        float t = 0.f;
        #pragma unroll
        for (int i = 0; i < 8; i++) t += wsum[i];
        g_normpart[blockIdx.x] = t;
    }
}

__global__ void k_prep(const float* __restrict__ ravg, const float* __restrict__ w) {
    __shared__ float red[256];
    int tid = threadIdx.x;
    red[tid] = g_normpart[tid];
    __syncthreads();
    for (int s = 128; s > 0; s >>= 1) {
        if (tid < s) red[tid] += red[tid + s];
        __syncthreads();
    }
    if (tid == 0) {
        float mean = red[0] / (float)BATCH;
        float ra = 0.99f * ravg[0] + 0.01f * mean;
        g_scale = 16.0f / ra;
        float s = 0.0f;
        for (int j = KB - 1; j >= 0; j--) { s += w[j]; g_cw[j] = s / (float)KB; }
        g_l1sum = 0.f; g_l0sum = 0.f;
    }
}

// fused: W_dec row norms + cw[seg] (blocks 0..NF/8-1), xn scaling (rest)
__global__ void k_wdnxn(const float* __restrict__ Wdec, const int* __restrict__ seg,
                        const float* __restrict__ x) {
    if (blockIdx.x < NF / 8) {
        int warp = threadIdx.x >> 5, lane = threadIdx.x & 31;
        int f = blockIdx.x * 8 + warp;
        const float* p = Wdec + f * DM + lane * 8;
        float4 v0 = *(const float4*)p;
        float4 v1 = *(const float4*)(p + 4);
        float s = v0.x*v0.x + v0.y*v0.y + v0.z*v0.z + v0.w*v0.w
                + v1.x*v1.x + v1.y*v1.y + v1.z*v1.z + v1.w*v1.w;
        #pragma unroll
        for (int o = 16; o > 0; o >>= 1) s += __shfl_down_sync(0xffffffffu, s, o);
        if (lane == 0) {
            g_wdn10[f] = 10.0f * sqrtf(s);
            g_cwseg[f] = g_cw[seg[f]];
        }
    } else {
        int i = (blockIdx.x - NF / 8) * 256 + threadIdx.x;
        float v = x[i] * g_scale;
        g_xn32[i] = v;
        g_xn[i] = __float2bfloat16(v);
    }
}

__global__ void k_worklist(const int* __restrict__ seg) {
    __shared__ int bpos[16];
    __shared__ int bcnt;
    int tid = threadIdx.x;
    if (tid == 0) bcnt = 0;
    if (tid < KB) g_errsum[tid] = 0.f;
    __syncthreads();
    for (int f = tid + 1; f < NF; f += blockDim.x) {
        if (seg[f] != seg[f - 1]) {
            int i = atomicAdd(&bcnt, 1);
            if (i < 16) bpos[i] = f;
        }
    }
    __syncthreads();
    if (tid == 0) {
        int n = bcnt < 16 ? bcnt : 16;
        for (int i = 1; i < n; i++) {
            int v = bpos[i], j = i - 1;
            while (j >= 0 && bpos[j] > v) { bpos[j + 1] = bpos[j]; j--; }
            bpos[j + 1] = v;
        }
        int cur = 0, bi = 0, ni = 0;
        while (cur < NF && ni < MAX_ITEMS) {
            int nxt = ((cur / CHUNK) + 1) * CHUNK;
            while (bi < n && bpos[bi] <= cur) bi++;
            if (bi < n && bpos[bi] < nxt) nxt = bpos[bi];
            g_items[ni * 4 + 0] = cur;
            g_items[ni * 4 + 1] = nxt - cur;
            g_items[ni * 4 + 2] = seg[cur];
            g_items[ni * 4 + 3] = 0;
            ni++; cur = nxt;
        }
        for (int i = 0; i < ni; i++)
            g_items[i * 4 + 3] = (i == ni - 1) || (g_items[(i + 1) * 4 + 2] != g_items[i * 4 + 2]);
        for (; ni < MAX_ITEMS; ni++) g_items[ni * 4 + 1] = 0;
    }
}

// transpose src[R][C] -> dst[C][R], fp32 -> bf16
__global__ void k_transpose(const float* __restrict__ src, int R, int C, int which) {
    __shared__ float t[32][33];
    __nv_bfloat16* dst = which ? g_WdecT : g_WencT;
    int bx = blockIdx.x * 32, by = blockIdx.y * 32;
    int x = threadIdx.x, y = threadIdx.y;
    #pragma unroll
    for (int j = 0; j < 32; j += 8) t[y + j][x] = src[(size_t)(by + y + j) * C + bx + x];
    __syncthreads();
    #pragma unroll
    for (int j = 0; j < 32; j += 8)
        dst[(size_t)(bx + y + j) * R + by + x] = __float2bfloat16(t[x][y + j]);
}

// ---------------- encode ----------------
// SMEM: 3 stages of (A 18432 + B 18432) @ 0/36864/73728, sArr @110592 (1536B)
#define ENC_SMEM (110592 + 1536)
#define DEC_SMEM 110592

__device__ __forceinline__ void enc_issue(uint32_t Ab, uint32_t Bb, int tid,
                                          int m0, int n0, int k0) {
    #pragma unroll
    for (int i = 0; i < 4; i++) {
        int slot = tid + i * 256, row = slot >> 3, c4 = slot & 7;
        uint32_t off = (uint32_t)(row * 144 + c4 * 16);
        cp16(Ab + off, &g_xn[(m0 + row) * DM + k0 + c4 * 8]);
        cp16(Bb + off, &g_WencT[(size_t)(n0 + row) * DM + k0 + c4 * 8]);
    }
    CP_COMMIT();
}

__global__ void __launch_bounds__(256, 2) k_encode(const float* __restrict__ benc) {
    extern __shared__ char smc[];
    uint32_t sb = (uint32_t)__cvta_generic_to_shared(smc);
    float* sArr = (float*)(smc + 110592);

    int tid = threadIdx.x, wid = tid >> 5, lane = tid & 31;
    int grp = lane >> 2, qid = lane & 3;
    int m0 = blockIdx.x * 128, n0 = blockIdx.y * 128;
    int rm = (wid & 3) * 32, rn = (wid >> 2) * 64;

    if (tid < 128) {
        sArr[tid]       = benc[n0 + tid];
        sArr[128 + tid] = g_wdn10[n0 + tid];
        sArr[256 + tid] = g_cwseg[n0 + tid];
    }

    float c[2][8][4];
    #pragma unroll
    for (int i = 0; i < 2; i++)
        #pragma unroll
        for (int j = 0; j < 8; j++)
            #pragma unroll
            for (int q = 0; q < 4; q++) c[i][j][q] = 0.f;

    // 3-stage ring, 2-deep prefetch, one sync per chunk
    enc_issue(sb, sb + 18432, tid, m0, n0, 0);
    enc_issue(sb + STG, sb + STG + 18432, tid, m0, n0, 64);

    #pragma unroll 1
    for (int s = 0; s < 4; s++) {
        CP_WAIT1();                       // stage s ready (2 groups were pending)
        __syncthreads();                  // all threads' copies done; frees buf (s-1)%3
        int nx = s + 2;
        if (nx < 4) {
            uint32_t base = sb + (uint32_t)(nx % 3) * STG;
            enc_issue(base, base + 18432, tid, m0, n0, nx * 64);
        } else CP_COMMIT();               // keep group count in lockstep
        uint32_t cb = (uint32_t)(s % 3) * STG;
        compute_chunk((const uint32_t*)(smc + cb), (const uint32_t*)(smc + cb + 18432),
                      rm, rn, grp, qid, c);
    }

    // epilogue: bias + relu + l1 via per-column log-of-product (16 logf, not 64) + l0
    float l1loc = 0.f;
    int l0loc = 0;
    #pragma unroll
    for (int ni = 0; ni < 8; ni++) {
        int nl = rn + ni * 8 + qid * 2;
        float be0 = sArr[nl], be1 = sArr[nl + 1];
        float wd0 = sArr[128 + nl], wd1 = sArr[128 + nl + 1];
        float cw0 = sArr[256 + nl], cw1 = sArr[256 + nl + 1];
        float p0 = 1.f, p1 = 1.f;
        #pragma unroll
        for (int mi = 0; mi < 2; mi++) {
            int mg = m0 + rm + mi * 16 + grp;
            #pragma unroll
            for (int h = 0; h < 2; h++) {
                int m = mg + h * 8;
                float a0 = fmaxf(c[mi][ni][h * 2 + 0] + be0, 0.f);
                float a1 = fmaxf(c[mi][ni][h * 2 + 1] + be1, 0.f);
                p0 *= fmaf(a0, wd0, 1.f);
                p1 *= fmaf(a1, wd1, 1.f);
                l0loc += (a0 > 0.f) + (a1 > 0.f);
                *(__nv_bfloat162*)&g_acts[(size_t)m * NF + n0 + nl] =
                    __floats2bfloat162_rn(a0, a1);
            }
        }
        l1loc += __logf(p0) * cw0 + __logf(p1) * cw1;
    }
    float l0f = (float)l0loc;
    #pragma unroll
    for (int o = 16; o > 0; o >>= 1) {
        l1loc += __shfl_down_sync(0xffffffffu, l1loc, o);
        l0f   += __shfl_down_sync(0xffffffffu, l0f, o);
    }
    if (lane == 0) { atomicAdd(&g_l1sum, l1loc); atomicAdd(&g_l0sum, l0f); }
}

// ---------------- decode ----------------
// bf16: fa = fs & ~7 (16B alignment); valid features [fs, fe); edges via scalar path.
__device__ __forceinline__ void dec_issue(uint32_t Ab, uint32_t Bb,
                                          __nv_bfloat16* Af, __nv_bfloat16* Bf,
                                          int tid, int m0, int d0,
                                          int fa, int lo, int hi, int k0) {
    int lo8 = lo ? 8 : 0;
    #pragma unroll
    for (int i = 0; i < 4; i++) {
        int slot = tid + i * 256, row = slot >> 3, c4 = slot & 7;
        int kb = k0 + c4 * 8;
        uint32_t off = (uint32_t)(row * 144 + c4 * 16);
        if (kb >= lo8 && kb + 7 < hi) {
            cp16(Ab + off, &g_acts[(size_t)(m0 + row) * NF + fa + kb]);
            cp16(Bb + off, &g_WdecT[(size_t)(d0 + row) * NF + fa + kb]);
        } else {
            #pragma unroll
            for (int e = 0; e < 8; e++) {
                int k = kb + e;
                bool v = (k >= lo) && (k < hi);
                __nv_bfloat16 av = v ? g_acts[(size_t)(m0 + row) * NF + fa + k] : __nv_bfloat16(0.f);
                __nv_bfloat16 bv = v ? g_WdecT[(size_t)(d0 + row) * NF + fa + k] : __nv_bfloat16(0.f);
                Af[row * 72 + c4 * 8 + e] = av;
                Bf[row * 72 + c4 * 8 + e] = bv;
            }
        }
    }
    CP_COMMIT();
}

__global__ void __launch_bounds__(256, 2) k_decode() {
    int item = blockIdx.z;
    int fs = g_items[item * 4 + 0], len = g_items[item * 4 + 1];
    if (len == 0) return;
    int fa = fs & ~7;
    int fe = fs + len;
    int lo = fs - fa, hi = fe - fa;
    int ns = (hi + 63) >> 6;

    extern __shared__ char smc[];
    uint32_t sb = (uint32_t)__cvta_generic_to_shared(smc);

    int tid = threadIdx.x, wid = tid >> 5, lane = tid & 31;
    int grp = lane >> 2, qid = lane & 3;
    int m0 = blockIdx.y * 128, d0 = blockIdx.x * 128;
    int rm = (wid & 3) * 32, rn = (wid >> 2) * 64;

    float c[2][8][4];
    #pragma unroll
    for (int i = 0; i < 2; i++)
        #pragma unroll
        for (int j = 0; j < 8; j++)
            #pragma unroll
            for (int q = 0; q < 4; q++) c[i][j][q] = 0.f;

    // 3-stage ring, 2-deep prefetch, one sync per chunk
    dec_issue(sb, sb + 18432, (__nv_bfloat16*)smc, (__nv_bfloat16*)(smc + 18432),
              tid, m0, d0, fa, lo, hi, 0);
    if (ns > 1)
        dec_issue(sb + STG, sb + STG + 18432, (__nv_bfloat16*)(smc + STG),
                  (__nv_bfloat16*)(smc + STG + 18432), tid, m0, d0, fa, lo, hi, 64);
    else CP_COMMIT();

    #pragma unroll 1
    for (int s = 0; s < ns; s++) {
        CP_WAIT1();
        __syncthreads();
        int nx = s + 2;
        if (nx < ns) {
            uint32_t boff = (uint32_t)(nx % 3) * STG;
            dec_issue(sb + boff, sb + boff + 18432, (__nv_bfloat16*)(smc + boff),
                      (__nv_bfloat16*)(smc + boff + 18432), tid, m0, d0, fa, lo, hi, nx * 64);
        } else CP_COMMIT();
        uint32_t cb = (uint32_t)(s % 3) * STG;
        compute_chunk((const uint32_t*)(smc + cb), (const uint32_t*)(smc + cb + 18432),
                      rm, rn, grp, qid, c);
    }

    __nv_bfloat16* pbase = &g_part[(size_t)item * BATCH * DM];
    #pragma unroll
    for (int mi = 0; mi < 2; mi++) {
        #pragma unroll
        for (int ni = 0; ni < 8; ni++) {
            int mg = m0 + rm + mi * 16 + grp;
            int col = d0 + rn + ni * 8 + qid * 2;
            *(__nv_bfloat162*)&pbase[(size_t)mg * DM + col] =
                __floats2bfloat162_rn(c[mi][ni][0], c[mi][ni][1]);
            *(__nv_bfloat162*)&pbase[(size_t)(mg + 8) * DM + col] =
                __floats2bfloat162_rn(c[mi][ni][2], c[mi][ni][3]);
        }
    }
}

// ---------------- cumulative item sum + per-block squared error ----------------
__global__ void k_err(const float* __restrict__ bdec) {
    int b = blockIdx.x, d = threadIdx.x;
    __shared__ float red[256];
    float xnv = g_xn32[b * DM + d];
    float cum = bdec[d];
    for (int i = 0; i < MAX_ITEMS; i++) {
        int len = g_items[i * 4 + 1];
        if (len == 0) break;
        cum += __bfloat162float(g_part[(size_t)i * BATCH * DM + (size_t)b * DM + d]);
        if (g_items[i * 4 + 3]) {
            float e = cum - xnv;
            red[d] = e * e;
            __syncthreads();
            for (int s = 128; s > 0; s >>= 1) {
                if (d < s) red[d] += red[d + s];
                __syncthreads();
            }
            if (d == 0) atomicAdd(&g_errsum[g_items[i * 4 + 2]], red[0]);
            __syncthreads();
        }
    }
}

__global__ void k_final(const float* __restrict__ w, const float* __restrict__ l1_scale,
                        float* __restrict__ out) {
    float mse = 0.0f;
    for (int k = 0; k < KB; k++) mse += (g_errsum[k] / (float)BATCH) * w[k];
    mse /= (float)KB;
    float l1 = g_l1sum / (float)BATCH;
    float avg_l0 = g_l0sum / (float)BATCH;
    float s = (avg_l0 < 100.0f) ? l1_scale[0] * (1.0f - 3e-4f)
                                : l1_scale[0] * (1.0f + 3e-4f);
    out[0] = mse + s * l1;
}

// ---------------- launch ----------------
extern "C" void kernel_launch(void* const* d_in, const int* in_sizes, int n_in,
                              void* d_out, int out_size) {
    const float* x    = (const float*)d_in[0];
    const float* Wenc = (const float*)d_in[1];
    const float* benc = (const float*)d_in[2];
    const float* Wdec = (const float*)d_in[3];
    const float* bdec = (const float*)d_in[4];
    const float* bw   = (const float*)d_in[5];
    const float* ravg = (const float*)d_in[6];
    const float* l1s  = (const float*)d_in[7];
    const int*   seg  = (const int*)d_in[8];
    float* out = (float*)d_out;

    cudaFuncSetAttribute(k_encode, cudaFuncAttributeMaxDynamicSharedMemorySize, ENC_SMEM);
    cudaFuncSetAttribute(k_decode, cudaFuncAttributeMaxDynamicSharedMemorySize, DEC_SMEM);

    k_transpose<<<dim3(NF / 32, DM / 32), dim3(32, 8)>>>(Wenc, DM, NF, 0);
    k_transpose<<<dim3(DM / 32, NF / 32), dim3(32, 8)>>>(Wdec, NF, DM, 1);
    k_norms<<<BATCH / 8, 256>>>(x);
    k_prep<<<1, 256>>>(ravg, bw);
    k_wdnxn<<<NF / 8 + BATCH * DM / 256, 256>>>(Wdec, seg, x);
    k_encode<<<dim3(16, 256), 256, ENC_SMEM>>>(benc);
    k_worklist<<<1, 256>>>(seg);
    k_decode<<<dim3(2, 16, MAX_ITEMS), 256, DEC_SMEM>>>();
    k_err<<<BATCH, 256>>>(bdec);
    k_final<<<1, 1>>>(bw, l1s, out);
}